// round 3
// baseline (speedup 1.0000x reference)
#include <cuda_runtime.h>

typedef unsigned long long u64;

#define LDIM 26
#define KCOMP 64
#define BN 262144
#define NITER 8
#define WFLOOR 1e-5f
#define VFLOOR 1e-6f
#define LOG_PI_C 47.784803726642978f   // 26 * log(2*pi)

#define NBLK_E 444            // estep blocks (128 thr = 4 warps), 3/SM * 148
#define TILE_E 64
#define NBLK_M 444            // mstat blocks (256 thr), 3/SM * 148
#define TILE_M 32
#define NSLOT (NBLK_M * 4)    // 1776 partial slots
#define OUT_N (KCOMP + KCOMP*LDIM + KCOMP*LDIM*LDIM + 1)   // 44993

// ---------------- packed fp32x2 helpers ----------------
__device__ __forceinline__ void fma2(u64& d, u64 a, u64 b) {
    asm("fma.rn.f32x2 %0, %1, %2, %0;" : "+l"(d) : "l"(a), "l"(b));
}
__device__ __forceinline__ u64 pack2(float lo, float hi) {
    u64 r; asm("mov.b64 %0, {%1, %2};" : "=l"(r) : "f"(lo), "f"(hi)); return r;
}
__device__ __forceinline__ void unpack2(float& lo, float& hi, u64 v) {
    asm("mov.b64 {%0, %1}, %2;" : "=f"(lo), "=f"(hi) : "l"(v));
}

// ---------------- device state (no allocation allowed) ----------------
__device__ float g_w[KCOMP];
__device__ float g_mu[KCOMP * LDIM];
__device__ float g_sig[KCOMP * LDIM];
__device__ float g_Phn[KCOMP * LDIM];    // -0.5 / sigma
__device__ float g_MP[KCOMP * LDIM];     // mu / sigma
__device__ float g_C[KCOMP];             // log w - 0.5*(LOG_PI + logdet + quad)
__device__ u64   g_post[BN * KCOMP / 2]; // 64 MiB posterior (row-major [B][64] f32)
__device__ u64   g_part[(size_t)NSLOT * KCOMP * 28];  // 25.4 MiB partials
__device__ float g_stat[KCOMP * 56];
__device__ float g_llp[NBLK_E];
__device__ float g_ll;

// ---------------- init: normalize w0, copy mu0 / sigma0 ----------------
__global__ void k_init(const float* __restrict__ w0,
                       const float* __restrict__ mu0,
                       const float* __restrict__ s0) {
    __shared__ float s_sum;
    if (threadIdx.x == 0) {
        float s = 0.f;
        for (int k = 0; k < KCOMP; k++) s += w0[k];
        s_sum = s;
    }
    __syncthreads();
    for (int i = threadIdx.x; i < KCOMP * LDIM; i += blockDim.x) {
        g_mu[i]  = mu0[i];
        g_sig[i] = s0[i];
    }
    if (threadIdx.x < KCOMP) g_w[threadIdx.x] = w0[threadIdx.x] / s_sum;
}

// ---------------- prep (initial only): per-component E-step params ----------
__global__ void k_prep() {
    int k = blockIdx.x;
    int lane = threadIdx.x;
    float ld = 0.f, qd = 0.f;
    if (lane < LDIM) {
        float sg = g_sig[k * LDIM + lane];
        float mu = g_mu[k * LDIM + lane];
        float pr = 1.0f / sg;
        g_Phn[k * LDIM + lane] = -0.5f * pr;
        g_MP[k * LDIM + lane] = mu * pr;
        ld = logf(sg);
        qd = mu * mu * pr;
    }
    #pragma unroll
    for (int o = 16; o; o >>= 1) {
        ld += __shfl_xor_sync(0xffffffffu, ld, o);
        qd += __shfl_xor_sync(0xffffffffu, qd, o);
    }
    if (lane == 0)
        g_C[k] = logf(g_w[k]) - 0.5f * (LOG_PI_C + ld + qd);
}

// ---------------- E-step: warp-per-row, lane owns comps 2*lane, 2*lane+1 ----
// smem tile row layout (per l, 16B): {x, x, x^2, x^2}  -> LDS.128 = both packed operands
__global__ void __launch_bounds__(128) k_estep(const float* __restrict__ x) {
    __shared__ __align__(16) float xt[TILE_E * 104];
    __shared__ float sll[4];
    int tid = threadIdx.x;
    int lane = tid & 31;
    int warp = tid >> 5;
    int c0 = 2 * lane;

    u64 MPp[LDIM], Php[LDIM];
    #pragma unroll
    for (int l = 0; l < LDIM; l++) {
        MPp[l] = pack2(g_MP[c0 * LDIM + l],  g_MP[(c0 + 1) * LDIM + l]);
        Php[l] = pack2(g_Phn[c0 * LDIM + l], g_Phn[(c0 + 1) * LDIM + l]);
    }
    u64 Cp = pack2(g_C[c0], g_C[c0 + 1]);
    float llacc = 0.f;

    for (int t = blockIdx.x; t < BN / TILE_E; t += NBLK_E) {
        int rowbase = t * TILE_E;
        __syncthreads();
        for (int i = tid; i < TILE_E * LDIM; i += 128) {
            int r = i / LDIM, c = i % LDIM;
            float v = x[rowbase * LDIM + i];
            float2* d = (float2*)(xt + r * 104 + c * 4);
            d[0] = make_float2(v, v);
            d[1] = make_float2(v * v, v * v);
        }
        __syncthreads();
        #pragma unroll 1
        for (int it = 0; it < 8; it++) {
            int r0 = warp * 16 + it * 2;
            const ulonglong2* A = (const ulonglong2*)(xt + r0 * 104);
            const ulonglong2* B = (const ulonglong2*)(xt + (r0 + 1) * 104);
            u64 na = Cp, nb = Cp;
            #pragma unroll
            for (int l = 0; l < LDIM; l++) {
                ulonglong2 va = A[l];
                ulonglong2 vb = B[l];
                fma2(na, va.x, MPp[l]);
                fma2(na, va.y, Php[l]);
                fma2(nb, vb.x, MPp[l]);
                fma2(nb, vb.y, Php[l]);
            }
            float a0, a1, b0, b1;
            unpack2(a0, a1, na);
            unpack2(b0, b1, nb);
            float ma = fmaxf(a0, a1);
            float mb = fmaxf(b0, b1);
            #pragma unroll
            for (int o = 16; o; o >>= 1) {
                ma = fmaxf(ma, __shfl_xor_sync(0xffffffffu, ma, o));
                mb = fmaxf(mb, __shfl_xor_sync(0xffffffffu, mb, o));
            }
            float ea0 = __expf(a0 - ma), ea1 = __expf(a1 - ma);
            float eb0 = __expf(b0 - mb), eb1 = __expf(b1 - mb);
            float sa = ea0 + ea1, sb = eb0 + eb1;
            #pragma unroll
            for (int o = 16; o; o >>= 1) {
                sa += __shfl_xor_sync(0xffffffffu, sa, o);
                sb += __shfl_xor_sync(0xffffffffu, sb, o);
            }
            float rsa = __frcp_rn(sa), rsb = __frcp_rn(sb);
            g_post[(size_t)(rowbase + r0) * 32 + lane]     = pack2(ea0 * rsa, ea1 * rsa);
            g_post[(size_t)(rowbase + r0 + 1) * 32 + lane] = pack2(eb0 * rsb, eb1 * rsb);
            if (lane == 0) llacc += __logf(sa) + ma + __logf(sb) + mb;
        }
    }
    if (lane == 0) sll[warp] = llacc;
    __syncthreads();
    if (tid == 0) {
        float t = 0.f;
        for (int i = 0; i < 4; i++) t += sll[i];
        g_llp[blockIdx.x] = t;
    }
}

// ---------------- M-step stats: thread = (k, row-group), all 53 stats packed --
// smem tile row layout (per quad q, 16B): {x[2q], x[2q+1], x2[2q], x2[2q+1]}
__global__ void __launch_bounds__(256) k_mstat(const float* __restrict__ x) {
    __shared__ __align__(16) float xt[TILE_M * 52];
    int tid = threadIdx.x;
    int k = tid & 63;
    int g = tid >> 6;   // 0..3, 8 rows each

    u64 accx[13], accxx[13];
    #pragma unroll
    for (int q = 0; q < 13; q++) { accx[q] = 0ull; accxx[q] = 0ull; }
    float z = 0.f;

    for (int t = blockIdx.x; t < BN / TILE_M; t += NBLK_M) {
        int rowbase = t * TILE_M;
        __syncthreads();
        for (int i = tid; i < TILE_M * LDIM; i += 256) {
            int r = i / LDIM, c = i % LDIM;
            float v = x[rowbase * LDIM + i];
            int off = r * 52 + (c >> 1) * 4 + (c & 1);
            xt[off] = v;
            xt[off + 2] = v * v;
        }
        __syncthreads();
        #pragma unroll
        for (int rr = 0; rr < 8; rr++) {
            int r = g * 8 + rr;
            float p = ((const float*)g_post)[(size_t)(rowbase + r) * KCOMP + k];
            u64 pp = pack2(p, p);
            z += p;
            const ulonglong2* V = (const ulonglong2*)(xt + r * 52);
            #pragma unroll
            for (int q = 0; q < 13; q++) {
                ulonglong2 v = V[q];
                fma2(accx[q], pp, v.x);
                fma2(accxx[q], pp, v.y);
            }
        }
    }
    int slot = blockIdx.x * 4 + g;
    u64* dst = g_part + ((size_t)slot * KCOMP + k) * 28;
    dst[0] = pack2(z, 0.f);
    #pragma unroll
    for (int q = 0; q < 13; q++) {
        dst[1 + q] = accx[q];    // floats 2+2q, 3+2q  -> px col l at float 2+l
        dst[14 + q] = accxx[q];  // floats 28+2q       -> pxx col l at float 28+l
    }
}

// ---------------- reduce partials: one block per k ----------------
__global__ void __launch_bounds__(256) k_reduce() {
    __shared__ float red[4][56];
    int bk = blockIdx.x;
    int tid = threadIdx.x;
    int j = tid & 63;
    int s = tid >> 6;
    if (j < 56) {
        float acc = 0.f;
        const float* base = (const float*)g_part;
        for (int slot = s; slot < NSLOT; slot += 4)
            acc += base[((size_t)slot * KCOMP + bk) * 56 + j];
        red[s][j] = acc;
    }
    __syncthreads();
    if (tid < 56)
        g_stat[bk * 56 + tid] = red[0][tid] + red[1][tid] + red[2][tid] + red[3][tid];
}

// ---------------- M-step finalize + prep for next E-step ----------------
__global__ void __launch_bounds__(256) k_mstep() {
    __shared__ float s_w[KCOMP];
    __shared__ float s_ab[2];
    __shared__ float s_llp[64];
    int tid = threadIdx.x;

    if (tid < KCOMP) {
        s_w[tid] = fmaxf(g_stat[tid * 56] * (1.0f / BN), WFLOOR);
        float l = 0.f;
        for (int i = tid; i < NBLK_E; i += 64) l += g_llp[i];
        s_llp[tid] = l;
    }
    __syncthreads();
    if (tid == 0) {
        float sum = 0.f, ll = 0.f;
        for (int k = 0; k < KCOMP; k++) { sum += s_w[k]; ll += s_llp[k]; }
        float sf = WFLOOR * KCOMP;
        float a = (1.0f - sf) / (sum - sf);
        s_ab[0] = a;
        s_ab[1] = WFLOOR * (1.0f - a);
        g_ll = ll;
    }
    __syncthreads();
    if (tid < KCOMP) g_w[tid] = s_ab[0] * s_w[tid] + s_ab[1];

    for (int idx = tid; idx < KCOMP * LDIM; idx += 256) {
        int k = idx / LDIM, l = idx % LDIM;
        float zi = 1.0f / g_stat[k * 56];
        float mu = g_stat[k * 56 + 2 + l] * zi;
        float sg = fmaxf(g_stat[k * 56 + 28 + l] * zi - mu * mu, VFLOOR);
        g_mu[idx] = mu;
        g_sig[idx] = sg;
    }
    __syncthreads();

    // fused prep: 8 warps, each handles k = warp, warp+8, ...
    int warp = tid >> 5, lane = tid & 31;
    for (int k = warp; k < KCOMP; k += 8) {
        float ld = 0.f, qd = 0.f;
        if (lane < LDIM) {
            float sg = g_sig[k * LDIM + lane];
            float mu = g_mu[k * LDIM + lane];
            float pr = 1.0f / sg;
            g_Phn[k * LDIM + lane] = -0.5f * pr;
            g_MP[k * LDIM + lane] = mu * pr;
            ld = logf(sg);
            qd = mu * mu * pr;
        }
        #pragma unroll
        for (int o = 16; o; o >>= 1) {
            ld += __shfl_xor_sync(0xffffffffu, ld, o);
            qd += __shfl_xor_sync(0xffffffffu, qd, o);
        }
        if (lane == 0)
            g_C[k] = logf(g_w[k]) - 0.5f * (LOG_PI_C + ld + qd);
    }
}

// ---------------- output: w | mu | diag-expanded sigma | ll ----------------
__global__ void k_write(float* __restrict__ out) {
    int i = blockIdx.x * 256 + threadIdx.x;
    if (i >= OUT_N) return;
    float v;
    if (i < KCOMP) {
        v = g_w[i];
    } else if (i < KCOMP + KCOMP * LDIM) {
        v = g_mu[i - KCOMP];
    } else if (i < KCOMP + KCOMP * LDIM + KCOMP * LDIM * LDIM) {
        int j = i - (KCOMP + KCOMP * LDIM);
        int k = j / (LDIM * LDIM);
        int rc = j % (LDIM * LDIM);
        int r = rc / LDIM, c = rc % LDIM;
        v = (r == c) ? g_sig[k * LDIM + r] : 0.f;
    } else {
        v = g_ll;
    }
    out[i] = v;
}

extern "C" void kernel_launch(void* const* d_in, const int* in_sizes, int n_in,
                              void* d_out, int out_size) {
    const float* x   = (const float*)d_in[0];
    const float* w0  = (const float*)d_in[1];
    const float* mu0 = (const float*)d_in[2];
    const float* s0  = (const float*)d_in[3];
    float* out = (float*)d_out;

    k_init<<<1, 256>>>(w0, mu0, s0);
    k_prep<<<KCOMP, 32>>>();
    for (int it = 0; it < NITER; it++) {
        k_estep<<<NBLK_E, 128>>>(x);
        k_mstat<<<NBLK_M, 256>>>(x);
        k_reduce<<<KCOMP, 256>>>();
        k_mstep<<<1, 256>>>();
    }
    k_write<<<(OUT_N + 255) / 256, 256>>>(out);
}

// round 4
// speedup vs baseline: 1.1024x; 1.1024x over previous
#include <cuda_runtime.h>

#define LDIM 26
#define KCOMP 64
#define BN 262144
#define NITER 8
#define WFLOOR 1e-5f
#define VFLOOR 1e-6f
#define LOG_PI_C 47.784803726642978f   // 26 * log(2*pi)

#define NBLK_E 444            // estep blocks, 128 thr
#define EWARPS (NBLK_E * 4)   // 1776 warps, chunk 148 rows
#define ECHUNK 148
#define NBLK_M 592            // mstat blocks, 256 thr
#define MCHUNKS (NBLK_M * 2)  // 1184 row-chunks
#define MCHUNK 222
#define NSLOT MCHUNKS
#define OUT_N (KCOMP + KCOMP*LDIM + KCOMP*LDIM*LDIM + 1)   // 44993

// ---------------- device state (no allocation allowed) ----------------
__device__ float g_w[KCOMP];
__device__ float g_mu[KCOMP * LDIM];
__device__ float g_sig[KCOMP * LDIM];
__device__ float g_Phn[KCOMP * LDIM];    // -0.5 / sigma
__device__ float g_MP[KCOMP * LDIM];     // mu / sigma
__device__ float g_C[KCOMP];             // log w - 0.5*(LOG_PI + logdet + quad)
__device__ __align__(16) float g_xe[(size_t)BN * 52];  // 54.5MB: 13xfloat4 {x,x2,x,x2}
__device__ __align__(16) float g_xm[(size_t)BN * 56];  // 58.7MB: {x[26],0,0 | x2[26],0,0}
__device__ float g_post[(size_t)BN * KCOMP];           // 64 MiB posterior
__device__ float g_part[(size_t)NSLOT * KCOMP * 54];   // 16.4MB partials
__device__ float g_stat[KCOMP * 54];
__device__ float g_llp[NBLK_E];
__device__ float g_ll;

// ---------------- init: normalize w0, copy mu0 / sigma0 ----------------
__global__ void k_init(const float* __restrict__ w0,
                       const float* __restrict__ mu0,
                       const float* __restrict__ s0) {
    __shared__ float s_sum;
    if (threadIdx.x == 0) {
        float s = 0.f;
        for (int k = 0; k < KCOMP; k++) s += w0[k];
        s_sum = s;
    }
    __syncthreads();
    for (int i = threadIdx.x; i < KCOMP * LDIM; i += blockDim.x) {
        g_mu[i]  = mu0[i];
        g_sig[i] = s0[i];
    }
    if (threadIdx.x < KCOMP) g_w[threadIdx.x] = w0[threadIdx.x] / s_sum;
}

// ---------------- pack x into estep/mstat layouts (once; x is constant) -----
__global__ void k_pack(const float* __restrict__ x) {
    int stride = gridDim.x * blockDim.x;
    int tid = blockIdx.x * blockDim.x + threadIdx.x;
    for (size_t i = tid; i < (size_t)BN * LDIM; i += stride) {
        int row = i / LDIM, c = i % LDIM;
        float v = x[i];
        float v2 = v * v;
        size_t eo = (size_t)row * 52 + (c >> 1) * 4 + ((c & 1) << 1);
        g_xe[eo] = v;
        g_xe[eo + 1] = v2;
        size_t mo = (size_t)row * 56 + c;
        g_xm[mo] = v;
        g_xm[mo + 28] = v2;
    }
    for (size_t r = tid; r < BN; r += stride) {
        g_xm[r * 56 + 26] = 0.f; g_xm[r * 56 + 27] = 0.f;
        g_xm[r * 56 + 54] = 0.f; g_xm[r * 56 + 55] = 0.f;
    }
}

// ---------------- prep (initial only) ----------------
__global__ void k_prep() {
    int k = blockIdx.x;
    int lane = threadIdx.x;
    float ld = 0.f, qd = 0.f;
    if (lane < LDIM) {
        float sg = g_sig[k * LDIM + lane];
        float mu = g_mu[k * LDIM + lane];
        float pr = 1.0f / sg;
        g_Phn[k * LDIM + lane] = -0.5f * pr;
        g_MP[k * LDIM + lane] = mu * pr;
        ld = logf(sg);
        qd = mu * mu * pr;
    }
    #pragma unroll
    for (int o = 16; o; o >>= 1) {
        ld += __shfl_xor_sync(0xffffffffu, ld, o);
        qd += __shfl_xor_sync(0xffffffffu, qd, o);
    }
    if (lane == 0)
        g_C[k] = logf(g_w[k]) - 0.5f * (LOG_PI_C + ld + qd);
}

// ---------------- E-step: warp-per-2-rows, lane owns k and k+32, no smem ----
__global__ void __launch_bounds__(128) k_estep() {
    __shared__ float sll[4];
    int tid = threadIdx.x;
    int lane = tid & 31;
    int warp = tid >> 5;
    int gw = blockIdx.x * 4 + warp;

    float MP0[LDIM], Ph0[LDIM], MP1[LDIM], Ph1[LDIM];
    #pragma unroll
    for (int l = 0; l < LDIM; l++) {
        MP0[l] = g_MP[lane * LDIM + l];
        Ph0[l] = g_Phn[lane * LDIM + l];
        MP1[l] = g_MP[(lane + 32) * LDIM + l];
        Ph1[l] = g_Phn[(lane + 32) * LDIM + l];
    }
    float C0 = g_C[lane], C1 = g_C[lane + 32];
    float llacc = 0.f;

    int s = gw * ECHUNK;
    int e = s + ECHUNK;
    if (e > BN) e = BN;
    for (int r0 = s; r0 < e; r0 += 2) {
        const float4* A = (const float4*)(g_xe + (size_t)r0 * 52);
        const float4* B = (const float4*)(g_xe + (size_t)(r0 + 1) * 52);
        float n00 = C0, n01 = C1, n10 = C0, n11 = C1;
        #pragma unroll
        for (int i = 0; i < 13; i++) {
            float4 a = A[i];
            float4 b = B[i];
            n00 = fmaf(a.x, MP0[2*i],   n00);
            n00 = fmaf(a.y, Ph0[2*i],   n00);
            n00 = fmaf(a.z, MP0[2*i+1], n00);
            n00 = fmaf(a.w, Ph0[2*i+1], n00);
            n01 = fmaf(a.x, MP1[2*i],   n01);
            n01 = fmaf(a.y, Ph1[2*i],   n01);
            n01 = fmaf(a.z, MP1[2*i+1], n01);
            n01 = fmaf(a.w, Ph1[2*i+1], n01);
            n10 = fmaf(b.x, MP0[2*i],   n10);
            n10 = fmaf(b.y, Ph0[2*i],   n10);
            n10 = fmaf(b.z, MP0[2*i+1], n10);
            n10 = fmaf(b.w, Ph0[2*i+1], n10);
            n11 = fmaf(b.x, MP1[2*i],   n11);
            n11 = fmaf(b.y, Ph1[2*i],   n11);
            n11 = fmaf(b.z, MP1[2*i+1], n11);
            n11 = fmaf(b.w, Ph1[2*i+1], n11);
        }
        float m0 = fmaxf(n00, n01);
        float m1 = fmaxf(n10, n11);
        #pragma unroll
        for (int o = 16; o; o >>= 1) {
            m0 = fmaxf(m0, __shfl_xor_sync(0xffffffffu, m0, o));
            m1 = fmaxf(m1, __shfl_xor_sync(0xffffffffu, m1, o));
        }
        float e00 = __expf(n00 - m0), e01 = __expf(n01 - m0);
        float e10 = __expf(n10 - m1), e11 = __expf(n11 - m1);
        float s0 = e00 + e01, s1 = e10 + e11;
        #pragma unroll
        for (int o = 16; o; o >>= 1) {
            s0 += __shfl_xor_sync(0xffffffffu, s0, o);
            s1 += __shfl_xor_sync(0xffffffffu, s1, o);
        }
        float rs0 = __frcp_rn(s0), rs1 = __frcp_rn(s1);
        float* P0 = g_post + (size_t)r0 * KCOMP;
        P0[lane]              = e00 * rs0;
        P0[lane + 32]         = e01 * rs0;
        P0[KCOMP + lane]      = e10 * rs1;
        P0[KCOMP + lane + 32] = e11 * rs1;
        if (lane == 0) llacc += __logf(s0) + m0 + __logf(s1) + m1;
    }
    if (lane == 0) sll[warp] = llacc;
    __syncthreads();
    if (tid == 0)
        g_llp[blockIdx.x] = sll[0] + sll[1] + sll[2] + sll[3];
}

// ---------------- M-step stats: warp = (khalf, h); no smem, no barriers -----
// thread: k = lane + 32*khalf; h=0: z+px (27 stats), h=1: pxx (26 stats)
__global__ void __launch_bounds__(256, 4) k_mstat() {
    int tid = threadIdx.x;
    int lane = tid & 31;
    int warp = tid >> 5;
    int khalf = warp & 1;
    int h = (warp >> 1) & 1;
    int rg = (blockIdx.x << 1) | (warp >> 2);
    int k = lane + (khalf << 5);

    float z = 0.f;
    float acc[28];
    #pragma unroll
    for (int j = 0; j < 28; j++) acc[j] = 0.f;

    int s = rg * MCHUNK;
    int e = s + MCHUNK;
    if (e > BN) e = BN;
    const float* xb = g_xm + h * 28;
    for (int r = s; r < e; r++) {
        float p = g_post[(size_t)r * KCOMP + k];
        const float4* V = (const float4*)(xb + (size_t)r * 56);
        z += p;
        #pragma unroll
        for (int i = 0; i < 7; i++) {
            float4 v = V[i];
            acc[4*i]   = fmaf(p, v.x, acc[4*i]);
            acc[4*i+1] = fmaf(p, v.y, acc[4*i+1]);
            acc[4*i+2] = fmaf(p, v.z, acc[4*i+2]);
            acc[4*i+3] = fmaf(p, v.w, acc[4*i+3]);
        }
    }
    float* dst = g_part + ((size_t)rg * KCOMP + k) * 54;
    if (h == 0) {
        dst[0] = z;
        #pragma unroll
        for (int j = 0; j < 26; j++) dst[1 + j] = acc[j];
    } else {
        #pragma unroll
        for (int j = 0; j < 26; j++) dst[27 + j] = acc[j];
    }
}

// ---------------- reduce partials: one block per k ----------------
__global__ void __launch_bounds__(256) k_reduce() {
    __shared__ float red[4][54];
    int bk = blockIdx.x;
    int tid = threadIdx.x;
    int j = tid & 63;
    int s = tid >> 6;
    if (j < 54) {
        float acc = 0.f;
        for (int slot = s; slot < NSLOT; slot += 4)
            acc += g_part[((size_t)slot * KCOMP + bk) * 54 + j];
        red[s][j] = acc;
    }
    __syncthreads();
    if (tid < 54)
        g_stat[bk * 54 + tid] = red[0][tid] + red[1][tid] + red[2][tid] + red[3][tid];
}

// ---------------- M-step finalize + fused prep ----------------
__global__ void __launch_bounds__(256) k_mstep() {
    __shared__ float s_w[KCOMP];
    __shared__ float s_ab[2];
    __shared__ float s_llp[64];
    int tid = threadIdx.x;

    if (tid < KCOMP) {
        s_w[tid] = fmaxf(g_stat[tid * 54] * (1.0f / BN), WFLOOR);
        float l = 0.f;
        for (int i = tid; i < NBLK_E; i += 64) l += g_llp[i];
        s_llp[tid] = l;
    }
    __syncthreads();
    if (tid == 0) {
        float sum = 0.f, ll = 0.f;
        for (int k = 0; k < KCOMP; k++) { sum += s_w[k]; ll += s_llp[k]; }
        float sf = WFLOOR * KCOMP;
        float a = (1.0f - sf) / (sum - sf);
        s_ab[0] = a;
        s_ab[1] = WFLOOR * (1.0f - a);
        g_ll = ll;
    }
    __syncthreads();
    if (tid < KCOMP) g_w[tid] = s_ab[0] * s_w[tid] + s_ab[1];

    for (int idx = tid; idx < KCOMP * LDIM; idx += 256) {
        int k = idx / LDIM, l = idx % LDIM;
        float zi = 1.0f / g_stat[k * 54];
        float mu = g_stat[k * 54 + 1 + l] * zi;
        float sg = fmaxf(g_stat[k * 54 + 27 + l] * zi - mu * mu, VFLOOR);
        g_mu[idx] = mu;
        g_sig[idx] = sg;
    }
    __syncthreads();

    int warp = tid >> 5, lane = tid & 31;
    for (int k = warp; k < KCOMP; k += 8) {
        float ld = 0.f, qd = 0.f;
        if (lane < LDIM) {
            float sg = g_sig[k * LDIM + lane];
            float mu = g_mu[k * LDIM + lane];
            float pr = 1.0f / sg;
            g_Phn[k * LDIM + lane] = -0.5f * pr;
            g_MP[k * LDIM + lane] = mu * pr;
            ld = logf(sg);
            qd = mu * mu * pr;
        }
        #pragma unroll
        for (int o = 16; o; o >>= 1) {
            ld += __shfl_xor_sync(0xffffffffu, ld, o);
            qd += __shfl_xor_sync(0xffffffffu, qd, o);
        }
        if (lane == 0)
            g_C[k] = logf(g_w[k]) - 0.5f * (LOG_PI_C + ld + qd);
    }
}

// ---------------- output: w | mu | diag-expanded sigma | ll ----------------
__global__ void k_write(float* __restrict__ out) {
    int i = blockIdx.x * 256 + threadIdx.x;
    if (i >= OUT_N) return;
    float v;
    if (i < KCOMP) {
        v = g_w[i];
    } else if (i < KCOMP + KCOMP * LDIM) {
        v = g_mu[i - KCOMP];
    } else if (i < KCOMP + KCOMP * LDIM + KCOMP * LDIM * LDIM) {
        int j = i - (KCOMP + KCOMP * LDIM);
        int k = j / (LDIM * LDIM);
        int rc = j % (LDIM * LDIM);
        int r = rc / LDIM, c = rc % LDIM;
        v = (r == c) ? g_sig[k * LDIM + r] : 0.f;
    } else {
        v = g_ll;
    }
    out[i] = v;
}

extern "C" void kernel_launch(void* const* d_in, const int* in_sizes, int n_in,
                              void* d_out, int out_size) {
    const float* x   = (const float*)d_in[0];
    const float* w0  = (const float*)d_in[1];
    const float* mu0 = (const float*)d_in[2];
    const float* s0  = (const float*)d_in[3];
    float* out = (float*)d_out;

    k_init<<<1, 256>>>(w0, mu0, s0);
    k_pack<<<592, 256>>>(x);
    k_prep<<<KCOMP, 32>>>();
    for (int it = 0; it < NITER; it++) {
        k_estep<<<NBLK_E, 128>>>();
        k_mstat<<<NBLK_M, 256>>>();
        k_reduce<<<KCOMP, 256>>>();
        k_mstep<<<1, 256>>>();
    }
    k_write<<<(OUT_N + 255) / 256, 256>>>(out);
}

// round 5
// speedup vs baseline: 1.7172x; 1.5577x over previous
#include <cuda_runtime.h>

#define LDIM 26
#define KCOMP 64
#define BN 262144
#define NITER 8
#define WFLOOR 1e-5f
#define VFLOOR 1e-6f
#define LOG_PI_C 47.784803726642978f   // 26 * log(2*pi)

#define NBLK_E 444            // estep blocks (128 thr = 4 warps)
#define TILE_E 64
#define NBLK_M 592            // mstat blocks (256 thr), 4 per SM
#define TILE_M 32
#define NTILE_M (BN / TILE_M) // 8192
#define NSLOT (NBLK_M * 2)    // 1184 partial slots (block x rowgrp)
#define OUT_N (KCOMP + KCOMP*LDIM + KCOMP*LDIM*LDIM + 1)   // 44993

// ---------------- device state (no allocation allowed) ----------------
__device__ float g_w[KCOMP];
__device__ float g_mu[KCOMP * LDIM];
__device__ float g_sig[KCOMP * LDIM];
__device__ float g_Phn[KCOMP * LDIM];    // -0.5 / sigma
__device__ float g_MP[KCOMP * LDIM];     // mu / sigma
__device__ float g_C[KCOMP];             // log w - 0.5*(LOG_PI + logdet + quad)
__device__ float g_post[(size_t)BN * KCOMP];          // 64 MiB posterior
__device__ float g_part[(size_t)NSLOT * KCOMP * 54];  // 16.4MB partials
__device__ float g_stat[KCOMP * 54];
__device__ float g_llp[NBLK_E];
__device__ float g_ll;

// ---------------- init: normalize w0, copy mu0 / sigma0 ----------------
__global__ void k_init(const float* __restrict__ w0,
                       const float* __restrict__ mu0,
                       const float* __restrict__ s0) {
    __shared__ float s_sum;
    if (threadIdx.x == 0) {
        float s = 0.f;
        for (int k = 0; k < KCOMP; k++) s += w0[k];
        s_sum = s;
    }
    __syncthreads();
    for (int i = threadIdx.x; i < KCOMP * LDIM; i += blockDim.x) {
        g_mu[i]  = mu0[i];
        g_sig[i] = s0[i];
    }
    if (threadIdx.x < KCOMP) g_w[threadIdx.x] = w0[threadIdx.x] / s_sum;
}

// ---------------- prep (initial only) ----------------
__global__ void k_prep() {
    int k = blockIdx.x;
    int lane = threadIdx.x;
    float ld = 0.f, qd = 0.f;
    if (lane < LDIM) {
        float sg = g_sig[k * LDIM + lane];
        float mu = g_mu[k * LDIM + lane];
        float pr = 1.0f / sg;
        g_Phn[k * LDIM + lane] = -0.5f * pr;
        g_MP[k * LDIM + lane] = mu * pr;
        ld = logf(sg);
        qd = mu * mu * pr;
    }
    #pragma unroll
    for (int o = 16; o; o >>= 1) {
        ld += __shfl_xor_sync(0xffffffffu, ld, o);
        qd += __shfl_xor_sync(0xffffffffu, qd, o);
    }
    if (lane == 0)
        g_C[k] = logf(g_w[k]) - 0.5f * (LOG_PI_C + ld + qd);
}

// ---------------- E-step: smem tile, warp-per-2-rows, lane owns k, k+32 -----
// smem row layout per pair i (16B): {x[2i], x2[2i], x[2i+1], x2[2i+1]}
__global__ void __launch_bounds__(128) k_estep(const float* __restrict__ x) {
    __shared__ __align__(16) float xt[TILE_E * 52];
    __shared__ float sll[4];
    int tid = threadIdx.x;
    int lane = tid & 31;
    int warp = tid >> 5;

    float MP0[LDIM], Ph0[LDIM], MP1[LDIM], Ph1[LDIM];
    #pragma unroll
    for (int l = 0; l < LDIM; l++) {
        MP0[l] = g_MP[lane * LDIM + l];
        Ph0[l] = g_Phn[lane * LDIM + l];
        MP1[l] = g_MP[(lane + 32) * LDIM + l];
        Ph1[l] = g_Phn[(lane + 32) * LDIM + l];
    }
    float C0 = g_C[lane], C1 = g_C[lane + 32];
    float llacc = 0.f;

    for (int t = blockIdx.x; t < BN / TILE_E; t += NBLK_E) {
        int rowbase = t * TILE_E;
        __syncthreads();
        for (int i = tid; i < TILE_E * LDIM; i += 128) {
            int r = i / LDIM, c = i % LDIM;
            float v = x[rowbase * LDIM + i];
            int off = r * 52 + (c >> 1) * 4 + ((c & 1) << 1);
            xt[off] = v;
            xt[off + 1] = v * v;
        }
        __syncthreads();
        #pragma unroll 1
        for (int it = 0; it < 8; it++) {
            int r0 = warp * 16 + it * 2;
            const float4* A = (const float4*)(xt + r0 * 52);
            const float4* B = (const float4*)(xt + (r0 + 1) * 52);
            float n00 = C0, n01 = C1, n10 = C0, n11 = C1;
            #pragma unroll
            for (int i = 0; i < 13; i++) {
                float4 a = A[i];
                float4 b = B[i];
                n00 = fmaf(a.x, MP0[2*i],   n00);
                n00 = fmaf(a.y, Ph0[2*i],   n00);
                n00 = fmaf(a.z, MP0[2*i+1], n00);
                n00 = fmaf(a.w, Ph0[2*i+1], n00);
                n01 = fmaf(a.x, MP1[2*i],   n01);
                n01 = fmaf(a.y, Ph1[2*i],   n01);
                n01 = fmaf(a.z, MP1[2*i+1], n01);
                n01 = fmaf(a.w, Ph1[2*i+1], n01);
                n10 = fmaf(b.x, MP0[2*i],   n10);
                n10 = fmaf(b.y, Ph0[2*i],   n10);
                n10 = fmaf(b.z, MP0[2*i+1], n10);
                n10 = fmaf(b.w, Ph0[2*i+1], n10);
                n11 = fmaf(b.x, MP1[2*i],   n11);
                n11 = fmaf(b.y, Ph1[2*i],   n11);
                n11 = fmaf(b.z, MP1[2*i+1], n11);
                n11 = fmaf(b.w, Ph1[2*i+1], n11);
            }
            float m0 = fmaxf(n00, n01);
            float m1 = fmaxf(n10, n11);
            #pragma unroll
            for (int o = 16; o; o >>= 1) {
                m0 = fmaxf(m0, __shfl_xor_sync(0xffffffffu, m0, o));
                m1 = fmaxf(m1, __shfl_xor_sync(0xffffffffu, m1, o));
            }
            float e00 = __expf(n00 - m0), e01 = __expf(n01 - m0);
            float e10 = __expf(n10 - m1), e11 = __expf(n11 - m1);
            float s0 = e00 + e01, s1 = e10 + e11;
            #pragma unroll
            for (int o = 16; o; o >>= 1) {
                s0 += __shfl_xor_sync(0xffffffffu, s0, o);
                s1 += __shfl_xor_sync(0xffffffffu, s1, o);
            }
            float rs0 = __frcp_rn(s0), rs1 = __frcp_rn(s1);
            float* P0 = g_post + (size_t)(rowbase + r0) * KCOMP;
            P0[lane]              = e00 * rs0;
            P0[lane + 32]         = e01 * rs0;
            P0[KCOMP + lane]      = e10 * rs1;
            P0[KCOMP + lane + 32] = e11 * rs1;
            if (lane == 0) llacc += __logf(s0) + m0 + __logf(s1) + m1;
        }
    }
    if (lane == 0) sll[warp] = llacc;
    __syncthreads();
    if (tid == 0)
        g_llp[blockIdx.x] = sll[0] + sll[1] + sll[2] + sll[3];
}

// ---------------- M-step stats: warp = (khalf, h, rowgrp); smem tile --------
// thread: k = lane + 32*khalf; h=0 accumulates z+px over x, h=1 pxx over x^2
__global__ void __launch_bounds__(256, 4) k_mstat(const float* __restrict__ x) {
    __shared__ __align__(16) float xs[TILE_M][28];
    __shared__ __align__(16) float x2s[TILE_M][28];
    int tid = threadIdx.x;
    int lane = tid & 31;
    int warp = tid >> 5;
    int khalf = warp & 1;
    int h = (warp >> 1) & 1;
    int rgrp = warp >> 2;            // 0 or 1 -> 16 rows each
    int k = lane + (khalf << 5);

    if (tid < TILE_M) {
        xs[tid][26] = 0.f;  xs[tid][27] = 0.f;
        x2s[tid][26] = 0.f; x2s[tid][27] = 0.f;
    }

    float z = 0.f;
    float acc[28];
    #pragma unroll
    for (int j = 0; j < 28; j++) acc[j] = 0.f;

    for (int t = blockIdx.x; t < NTILE_M; t += NBLK_M) {
        int rowbase = t * TILE_M;
        __syncthreads();
        // stage 32 rows x 26 floats = 208 float4 loads
        if (tid < 208) {
            float4 v = ((const float4*)(x + (size_t)rowbase * LDIM))[tid];
            int e = tid * 4;
            float vv[4] = {v.x, v.y, v.z, v.w};
            #pragma unroll
            for (int j = 0; j < 4; j++) {
                int idx = e + j;
                int r = idx / LDIM, c = idx % LDIM;
                xs[r][c] = vv[j];
                x2s[r][c] = vv[j] * vv[j];
            }
        }
        __syncthreads();
        #pragma unroll
        for (int rr = 0; rr < 16; rr++) {
            int r = rgrp * 16 + rr;
            float p = g_post[(size_t)(rowbase + r) * KCOMP + k];
            z += p;
            const float4* V = (const float4*)(h ? x2s[r] : xs[r]);
            #pragma unroll
            for (int i = 0; i < 7; i++) {
                float4 v = V[i];
                acc[4*i]   = fmaf(p, v.x, acc[4*i]);
                acc[4*i+1] = fmaf(p, v.y, acc[4*i+1]);
                acc[4*i+2] = fmaf(p, v.z, acc[4*i+2]);
                acc[4*i+3] = fmaf(p, v.w, acc[4*i+3]);
            }
        }
    }
    int slot = blockIdx.x * 2 + rgrp;
    float* dst = g_part + ((size_t)slot * KCOMP + k) * 54;
    if (h == 0) {
        dst[0] = z;
        #pragma unroll
        for (int j = 0; j < 26; j++) dst[1 + j] = acc[j];
    } else {
        #pragma unroll
        for (int j = 0; j < 26; j++) dst[27 + j] = acc[j];
    }
}

// ---------------- reduce partials: one block per k ----------------
__global__ void __launch_bounds__(256) k_reduce() {
    __shared__ float red[4][54];
    int bk = blockIdx.x;
    int tid = threadIdx.x;
    int j = tid & 63;
    int s = tid >> 6;
    if (j < 54) {
        float acc = 0.f;
        for (int slot = s; slot < NSLOT; slot += 4)
            acc += g_part[((size_t)slot * KCOMP + bk) * 54 + j];
        red[s][j] = acc;
    }
    __syncthreads();
    if (tid < 54)
        g_stat[bk * 54 + tid] = red[0][tid] + red[1][tid] + red[2][tid] + red[3][tid];
}

// ---------------- M-step finalize + fused prep ----------------
__global__ void __launch_bounds__(256) k_mstep() {
    __shared__ float s_w[KCOMP];
    __shared__ float s_ab[2];
    __shared__ float s_llp[64];
    int tid = threadIdx.x;

    if (tid < KCOMP) {
        s_w[tid] = fmaxf(g_stat[tid * 54] * (1.0f / BN), WFLOOR);
        float l = 0.f;
        for (int i = tid; i < NBLK_E; i += 64) l += g_llp[i];
        s_llp[tid] = l;
    }
    __syncthreads();
    if (tid == 0) {
        float sum = 0.f, ll = 0.f;
        for (int k = 0; k < KCOMP; k++) { sum += s_w[k]; ll += s_llp[k]; }
        float sf = WFLOOR * KCOMP;
        float a = (1.0f - sf) / (sum - sf);
        s_ab[0] = a;
        s_ab[1] = WFLOOR * (1.0f - a);
        g_ll = ll;
    }
    __syncthreads();
    if (tid < KCOMP) g_w[tid] = s_ab[0] * s_w[tid] + s_ab[1];

    for (int idx = tid; idx < KCOMP * LDIM; idx += 256) {
        int k = idx / LDIM, l = idx % LDIM;
        float zi = 1.0f / g_stat[k * 54];
        float mu = g_stat[k * 54 + 1 + l] * zi;
        float sg = fmaxf(g_stat[k * 54 + 27 + l] * zi - mu * mu, VFLOOR);
        g_mu[idx] = mu;
        g_sig[idx] = sg;
    }
    __syncthreads();

    int warp = tid >> 5, lane = tid & 31;
    for (int k = warp; k < KCOMP; k += 8) {
        float ld = 0.f, qd = 0.f;
        if (lane < LDIM) {
            float sg = g_sig[k * LDIM + lane];
            float mu = g_mu[k * LDIM + lane];
            float pr = 1.0f / sg;
            g_Phn[k * LDIM + lane] = -0.5f * pr;
            g_MP[k * LDIM + lane] = mu * pr;
            ld = logf(sg);
            qd = mu * mu * pr;
        }
        #pragma unroll
        for (int o = 16; o; o >>= 1) {
            ld += __shfl_xor_sync(0xffffffffu, ld, o);
            qd += __shfl_xor_sync(0xffffffffu, qd, o);
        }
        if (lane == 0)
            g_C[k] = logf(g_w[k]) - 0.5f * (LOG_PI_C + ld + qd);
    }
}

// ---------------- output: w | mu | diag-expanded sigma | ll ----------------
__global__ void k_write(float* __restrict__ out) {
    int i = blockIdx.x * 256 + threadIdx.x;
    if (i >= OUT_N) return;
    float v;
    if (i < KCOMP) {
        v = g_w[i];
    } else if (i < KCOMP + KCOMP * LDIM) {
        v = g_mu[i - KCOMP];
    } else if (i < KCOMP + KCOMP * LDIM + KCOMP * LDIM * LDIM) {
        int j = i - (KCOMP + KCOMP * LDIM);
        int k = j / (LDIM * LDIM);
        int rc = j % (LDIM * LDIM);
        int r = rc / LDIM, c = rc % LDIM;
        v = (r == c) ? g_sig[k * LDIM + r] : 0.f;
    } else {
        v = g_ll;
    }
    out[i] = v;
}

extern "C" void kernel_launch(void* const* d_in, const int* in_sizes, int n_in,
                              void* d_out, int out_size) {
    const float* x   = (const float*)d_in[0];
    const float* w0  = (const float*)d_in[1];
    const float* mu0 = (const float*)d_in[2];
    const float* s0  = (const float*)d_in[3];
    float* out = (float*)d_out;

    k_init<<<1, 256>>>(w0, mu0, s0);
    k_prep<<<KCOMP, 32>>>();
    for (int it = 0; it < NITER; it++) {
        k_estep<<<NBLK_E, 128>>>(x);
        k_mstat<<<NBLK_M, 256>>>(x);
        k_reduce<<<KCOMP, 256>>>();
        k_mstep<<<1, 256>>>();
    }
    k_write<<<(OUT_N + 255) / 256, 256>>>(out);
}

// round 7
// speedup vs baseline: 1.8815x; 1.0957x over previous
#include <cuda_runtime.h>

#define LDIM 26
#define KCOMP 64
#define BN 262144
#define NITER 8
#define WFLOOR 1e-5f
#define VFLOOR 1e-6f
#define LOG_PI_C 47.784803726642978f   // 26 * log(2*pi)

#define NBLK_E 444            // estep blocks (128 thr = 4 warps)
#define TILE_E 128
#define NBLK_M 592            // mstat blocks (256 thr), 4 per SM
#define TILE_M 32
#define NTILE_M (BN / TILE_M) // 8192
#define NSLOT NBLK_M          // 592 partial slots (one per block)
#define OUT_N (KCOMP + KCOMP*LDIM + KCOMP*LDIM*LDIM + 1)   // 44993

// ---------------- device state (no allocation allowed) ----------------
__device__ float g_w[KCOMP];
__device__ float g_mu[KCOMP * LDIM];
__device__ float g_sig[KCOMP * LDIM];
__device__ float g_Phn[KCOMP * LDIM];    // -0.5 / sigma
__device__ float g_MP[KCOMP * LDIM];     // mu / sigma
__device__ float g_C[KCOMP];             // log w - 0.5*(LOG_PI + logdet + quad)
__device__ float g_post[(size_t)BN * KCOMP];          // 64 MiB posterior
__device__ float g_part[(size_t)NSLOT * KCOMP * 54];  // 8.2MB partials
__device__ float g_stat[KCOMP * 54];
__device__ float g_llp[NBLK_E];
__device__ float g_ll;

// ---------------- init: normalize w0, copy mu0 / sigma0 ----------------
__global__ void k_init(const float* __restrict__ w0,
                       const float* __restrict__ mu0,
                       const float* __restrict__ s0) {
    __shared__ float s_sum;
    if (threadIdx.x == 0) {
        float s = 0.f;
        for (int k = 0; k < KCOMP; k++) s += w0[k];
        s_sum = s;
    }
    __syncthreads();
    for (int i = threadIdx.x; i < KCOMP * LDIM; i += blockDim.x) {
        g_mu[i]  = mu0[i];
        g_sig[i] = s0[i];
    }
    if (threadIdx.x < KCOMP) g_w[threadIdx.x] = w0[threadIdx.x] / s_sum;
}

// ---------------- prep (initial only) ----------------
__global__ void k_prep() {
    int k = blockIdx.x;
    int lane = threadIdx.x;
    float ld = 0.f, qd = 0.f;
    if (lane < LDIM) {
        float sg = g_sig[k * LDIM + lane];
        float mu = g_mu[k * LDIM + lane];
        float pr = 1.0f / sg;
        g_Phn[k * LDIM + lane] = -0.5f * pr;
        g_MP[k * LDIM + lane] = mu * pr;
        ld = logf(sg);
        qd = mu * mu * pr;
    }
    #pragma unroll
    for (int o = 16; o; o >>= 1) {
        ld += __shfl_xor_sync(0xffffffffu, ld, o);
        qd += __shfl_xor_sync(0xffffffffu, qd, o);
    }
    if (lane == 0)
        g_C[k] = logf(g_w[k]) - 0.5f * (LOG_PI_C + ld + qd);
}

// ---------------- E-step: x-only smem tile, warp-per-2-rows ----------------
// n[k] = C[k] + sum_l x * (MP[k][l] + x * Phn[k][l]);  params padded to 28
// with zeros so lanes 26/27 contribute exactly 0 regardless of pad x values.
__global__ void __launch_bounds__(128) k_estep(const float* __restrict__ x) {
    __shared__ __align__(16) float xt[TILE_E * 28];
    __shared__ float sll[4];
    int tid = threadIdx.x;
    int lane = tid & 31;
    int warp = tid >> 5;

    // zero pads once (staging never writes c>=26)
    for (int r = tid; r < TILE_E; r += 128) {
        xt[r * 28 + 26] = 0.f;
        xt[r * 28 + 27] = 0.f;
    }

    float MP0[28], Ph0[28], MP1[28], Ph1[28];
    #pragma unroll
    for (int l = 0; l < LDIM; l++) {
        MP0[l] = g_MP[lane * LDIM + l];
        Ph0[l] = g_Phn[lane * LDIM + l];
        MP1[l] = g_MP[(lane + 32) * LDIM + l];
        Ph1[l] = g_Phn[(lane + 32) * LDIM + l];
    }
    #pragma unroll
    for (int l = LDIM; l < 28; l++) {
        MP0[l] = 0.f; Ph0[l] = 0.f; MP1[l] = 0.f; Ph1[l] = 0.f;
    }
    float C0 = g_C[lane], C1 = g_C[lane + 32];
    float llacc = 0.f;

    for (int t = blockIdx.x; t < BN / TILE_E; t += NBLK_E) {
        int rowbase = t * TILE_E;
        __syncthreads();
        // stage 128 rows x 26 floats = 832 float4
        const float4* src = (const float4*)(x + (size_t)rowbase * LDIM);
        for (int i = tid; i < TILE_E * LDIM / 4; i += 128) {
            float4 v = src[i];
            int e = i * 4;
            float vv[4] = {v.x, v.y, v.z, v.w};
            #pragma unroll
            for (int j = 0; j < 4; j++) {
                int idx = e + j;
                int r = idx / LDIM, c = idx % LDIM;
                xt[r * 28 + c] = vv[j];
            }
        }
        __syncthreads();
        #pragma unroll 1
        for (int it = 0; it < 16; it++) {
            int r0 = warp * 32 + it * 2;
            const float4* A = (const float4*)(xt + r0 * 28);
            const float4* B = (const float4*)(xt + (r0 + 1) * 28);
            float n00 = C0, n01 = C1, n10 = C0, n11 = C1;
            #pragma unroll
            for (int i = 0; i < 7; i++) {
                float4 a = A[i];
                float4 b = B[i];
                #pragma unroll
                for (int j = 0; j < 4; j++) {
                    int l = 4 * i + j;
                    float ax = j == 0 ? a.x : j == 1 ? a.y : j == 2 ? a.z : a.w;
                    float bx = j == 0 ? b.x : j == 1 ? b.y : j == 2 ? b.z : b.w;
                    float t0 = fmaf(ax, Ph0[l], MP0[l]);
                    n00 = fmaf(ax, t0, n00);
                    float t1 = fmaf(ax, Ph1[l], MP1[l]);
                    n01 = fmaf(ax, t1, n01);
                    float u0 = fmaf(bx, Ph0[l], MP0[l]);
                    n10 = fmaf(bx, u0, n10);
                    float u1 = fmaf(bx, Ph1[l], MP1[l]);
                    n11 = fmaf(bx, u1, n11);
                }
            }
            float m0 = fmaxf(n00, n01);
            float m1 = fmaxf(n10, n11);
            #pragma unroll
            for (int o = 16; o; o >>= 1) {
                m0 = fmaxf(m0, __shfl_xor_sync(0xffffffffu, m0, o));
                m1 = fmaxf(m1, __shfl_xor_sync(0xffffffffu, m1, o));
            }
            float e00 = __expf(n00 - m0), e01 = __expf(n01 - m0);
            float e10 = __expf(n10 - m1), e11 = __expf(n11 - m1);
            float s0 = e00 + e01, s1 = e10 + e11;
            #pragma unroll
            for (int o = 16; o; o >>= 1) {
                s0 += __shfl_xor_sync(0xffffffffu, s0, o);
                s1 += __shfl_xor_sync(0xffffffffu, s1, o);
            }
            float rs0 = __frcp_rn(s0), rs1 = __frcp_rn(s1);
            float* P0 = g_post + (size_t)(rowbase + r0) * KCOMP;
            P0[lane]              = e00 * rs0;
            P0[lane + 32]         = e01 * rs0;
            P0[KCOMP + lane]      = e10 * rs1;
            P0[KCOMP + lane + 32] = e11 * rs1;
            if (lane == 0) llacc += __logf(s0) + m0 + __logf(s1) + m1;
        }
    }
    if (lane == 0) sll[warp] = llacc;
    __syncthreads();
    if (tid == 0)
        g_llp[blockIdx.x] = sll[0] + sll[1] + sll[2] + sll[3];
}

// ---------------- M-step stats: warp = (khalf, h, rowgrp); p staged in smem -
// thread: k = lane + 32*khalf; h=0 accumulates z+px over x, h=1 pxx over x^2
__global__ void __launch_bounds__(256, 4) k_mstat(const float* __restrict__ x) {
    __shared__ __align__(16) float xs[TILE_M][28];
    __shared__ __align__(16) float x2s[TILE_M][28];
    __shared__ __align__(16) float ps[TILE_M][KCOMP];
    __shared__ float comb[128 * 29];
    int tid = threadIdx.x;
    int lane = tid & 31;
    int warp = tid >> 5;
    int khalf = warp & 1;
    int h = (warp >> 1) & 1;
    int rgrp = warp >> 2;            // 0 or 1 -> 16 rows each
    int k = lane + (khalf << 5);

    if (tid < TILE_M) {
        xs[tid][26] = 0.f;  xs[tid][27] = 0.f;
        x2s[tid][26] = 0.f; x2s[tid][27] = 0.f;
    }

    float z = 0.f;
    float acc[28];
    #pragma unroll
    for (int j = 0; j < 28; j++) acc[j] = 0.f;

    for (int t = blockIdx.x; t < NTILE_M; t += NBLK_M) {
        int rowbase = t * TILE_M;
        __syncthreads();
        // stage 32 rows x 26 floats = 208 float4
        if (tid < 208) {
            float4 v = ((const float4*)(x + (size_t)rowbase * LDIM))[tid];
            int e = tid * 4;
            float vv[4] = {v.x, v.y, v.z, v.w};
            #pragma unroll
            for (int j = 0; j < 4; j++) {
                int idx = e + j;
                int r = idx / LDIM, c = idx % LDIM;
                xs[r][c] = vv[j];
                x2s[r][c] = vv[j] * vv[j];
            }
        }
        // stage 32 rows x 64 posteriors = 512 float4
        {
            const float4* psrc = (const float4*)(g_post + (size_t)rowbase * KCOMP);
            float4 p0 = psrc[tid];
            float4 p1 = psrc[tid + 256];
            ((float4*)ps)[tid] = p0;
            ((float4*)ps)[tid + 256] = p1;
        }
        __syncthreads();
        #pragma unroll
        for (int rr = 0; rr < 16; rr++) {
            int r = rgrp * 16 + rr;
            float p = ps[r][k];
            z += p;
            const float4* V = (const float4*)(h ? x2s[r] : xs[r]);
            #pragma unroll
            for (int i = 0; i < 7; i++) {
                float4 v = V[i];
                acc[4*i]   = fmaf(p, v.x, acc[4*i]);
                acc[4*i+1] = fmaf(p, v.y, acc[4*i+1]);
                acc[4*i+2] = fmaf(p, v.z, acc[4*i+2]);
                acc[4*i+3] = fmaf(p, v.w, acc[4*i+3]);
            }
        }
    }
    // combine rgrp=1 into rgrp=0 via smem, then one partial slot per block
    __syncthreads();
    if (rgrp == 1) {
        float* c = comb + ((warp & 3) * 32 + lane) * 29;
        #pragma unroll
        for (int j = 0; j < 26; j++) c[j] = acc[j];
        c[26] = z;
    }
    __syncthreads();
    if (rgrp == 0) {
        const float* c = comb + (warp * 32 + lane) * 29;
        #pragma unroll
        for (int j = 0; j < 26; j++) acc[j] += c[j];
        z += c[26];
        float* dst = g_part + ((size_t)blockIdx.x * KCOMP + k) * 54;
        if (h == 0) {
            dst[0] = z;
            #pragma unroll
            for (int j = 0; j < 26; j++) dst[1 + j] = acc[j];
        } else {
            #pragma unroll
            for (int j = 0; j < 26; j++) dst[27 + j] = acc[j];
        }
    }
}

// ---------------- reduce partials: one block per k ----------------
__global__ void __launch_bounds__(256) k_reduce() {
    __shared__ float red[4][54];
    int bk = blockIdx.x;
    int tid = threadIdx.x;
    int j = tid & 63;
    int s = tid >> 6;
    if (j < 54) {
        float acc = 0.f;
        for (int slot = s; slot < NSLOT; slot += 4)
            acc += g_part[((size_t)slot * KCOMP + bk) * 54 + j];
        red[s][j] = acc;
    }
    __syncthreads();
    if (tid < 54)
        g_stat[bk * 54 + tid] = red[0][tid] + red[1][tid] + red[2][tid] + red[3][tid];
}

// ---------------- M-step finalize + fused prep ----------------
__global__ void __launch_bounds__(256) k_mstep() {
    __shared__ float s_w[KCOMP];
    __shared__ float s_ab[2];
    __shared__ float s_llp[64];
    int tid = threadIdx.x;

    if (tid < KCOMP) {
        s_w[tid] = fmaxf(g_stat[tid * 54] * (1.0f / BN), WFLOOR);
        float l = 0.f;
        for (int i = tid; i < NBLK_E; i += 64) l += g_llp[i];
        s_llp[tid] = l;
    }
    __syncthreads();
    if (tid == 0) {
        float sum = 0.f, ll = 0.f;
        for (int k = 0; k < KCOMP; k++) { sum += s_w[k]; ll += s_llp[k]; }
        float sf = WFLOOR * KCOMP;
        float a = (1.0f - sf) / (sum - sf);
        s_ab[0] = a;
        s_ab[1] = WFLOOR * (1.0f - a);
        g_ll = ll;
    }
    __syncthreads();
    if (tid < KCOMP) g_w[tid] = s_ab[0] * s_w[tid] + s_ab[1];

    for (int idx = tid; idx < KCOMP * LDIM; idx += 256) {
        int k = idx / LDIM, l = idx % LDIM;
        float zi = 1.0f / g_stat[k * 54];
        float mu = g_stat[k * 54 + 1 + l] * zi;
        float sg = fmaxf(g_stat[k * 54 + 27 + l] * zi - mu * mu, VFLOOR);
        g_mu[idx] = mu;
        g_sig[idx] = sg;
    }
    __syncthreads();

    int warp = tid >> 5, lane = tid & 31;
    for (int k = warp; k < KCOMP; k += 8) {
        float ld = 0.f, qd = 0.f;
        if (lane < LDIM) {
            float sg = g_sig[k * LDIM + lane];
            float mu = g_mu[k * LDIM + lane];
            float pr = 1.0f / sg;
            g_Phn[k * LDIM + lane] = -0.5f * pr;
            g_MP[k * LDIM + lane] = mu * pr;
            ld = logf(sg);
            qd = mu * mu * pr;
        }
        #pragma unroll
        for (int o = 16; o; o >>= 1) {
            ld += __shfl_xor_sync(0xffffffffu, ld, o);
            qd += __shfl_xor_sync(0xffffffffu, qd, o);
        }
        if (lane == 0)
            g_C[k] = logf(g_w[k]) - 0.5f * (LOG_PI_C + ld + qd);
    }
}

// ---------------- output: w | mu | diag-expanded sigma | ll ----------------
__global__ void k_write(float* __restrict__ out) {
    int i = blockIdx.x * 256 + threadIdx.x;
    if (i >= OUT_N) return;
    float v;
    if (i < KCOMP) {
        v = g_w[i];
    } else if (i < KCOMP + KCOMP * LDIM) {
        v = g_mu[i - KCOMP];
    } else if (i < KCOMP + KCOMP * LDIM + KCOMP * LDIM * LDIM) {
        int j = i - (KCOMP + KCOMP * LDIM);
        int k = j / (LDIM * LDIM);
        int rc = j % (LDIM * LDIM);
        int r = rc / LDIM, c = rc % LDIM;
        v = (r == c) ? g_sig[k * LDIM + r] : 0.f;
    } else {
        v = g_ll;
    }
    out[i] = v;
}

extern "C" void kernel_launch(void* const* d_in, const int* in_sizes, int n_in,
                              void* d_out, int out_size) {
    const float* x   = (const float*)d_in[0];
    const float* w0  = (const float*)d_in[1];
    const float* mu0 = (const float*)d_in[2];
    const float* s0  = (const float*)d_in[3];
    float* out = (float*)d_out;

    k_init<<<1, 256>>>(w0, mu0, s0);
    k_prep<<<KCOMP, 32>>>();
    for (int it = 0; it < NITER; it++) {
        k_estep<<<NBLK_E, 128>>>(x);
        k_mstat<<<NBLK_M, 256>>>(x);
        k_reduce<<<KCOMP, 256>>>();
        k_mstep<<<1, 256>>>();
    }
    k_write<<<(OUT_N + 255) / 256, 256>>>(out);
}

// round 8
// speedup vs baseline: 2.0058x; 1.0661x over previous
#include <cuda_runtime.h>

#define LDIM 26
#define KCOMP 64
#define BN 262144
#define NITER 8
#define WFLOOR 1e-5f
#define VFLOOR 1e-6f
#define LOG_PI_C 47.784803726642978f   // 26 * log(2*pi)
#define SHIFT 40.0f                    // fixed logit shift (replaces per-row max)

#define NBLK_E 444            // estep blocks (128 thr = 4 warps)
#define TILE_E 128
#define NBLK_M 592            // mstat blocks (256 thr), 4 per SM
#define TILE_M 32
#define NTILE_M (BN / TILE_M) // 8192
#define NSLOT NBLK_M          // 592 partial slots (one per block)
#define RHALF (NSLOT / 2)     // 296 slots per reduce-half
#define OUT_N (KCOMP + KCOMP*LDIM + KCOMP*LDIM*LDIM + 1)   // 44993

// ---------------- device state (no allocation allowed) ----------------
__device__ float g_w[KCOMP];
__device__ float g_mu[KCOMP * LDIM];
__device__ float g_sig[KCOMP * LDIM];
__device__ float g_Phn[KCOMP * LDIM];    // -0.5 / sigma
__device__ float g_MP[KCOMP * LDIM];     // mu / sigma
__device__ float g_C[KCOMP];             // log w - 0.5*(LOG_PI + logdet + quad) + SHIFT
__device__ float g_post[(size_t)BN * KCOMP];          // 64 MiB posterior
__device__ float g_part[(size_t)NSLOT * KCOMP * 54];  // 8.2MB partials
__device__ float g_stat2[2][KCOMP * 54];
__device__ float g_llp[NBLK_E];
__device__ float g_ll;

// ---------------- init: normalize w0, copy mu0 / sigma0 ----------------
__global__ void k_init(const float* __restrict__ w0,
                       const float* __restrict__ mu0,
                       const float* __restrict__ s0) {
    __shared__ float s_sum;
    if (threadIdx.x == 0) {
        float s = 0.f;
        for (int k = 0; k < KCOMP; k++) s += w0[k];
        s_sum = s;
    }
    __syncthreads();
    for (int i = threadIdx.x; i < KCOMP * LDIM; i += blockDim.x) {
        g_mu[i]  = mu0[i];
        g_sig[i] = s0[i];
    }
    if (threadIdx.x < KCOMP) g_w[threadIdx.x] = w0[threadIdx.x] / s_sum;
}

// ---------------- prep (initial only) ----------------
__global__ void k_prep() {
    int k = blockIdx.x;
    int lane = threadIdx.x;
    float ld = 0.f, qd = 0.f;
    if (lane < LDIM) {
        float sg = g_sig[k * LDIM + lane];
        float mu = g_mu[k * LDIM + lane];
        float pr = 1.0f / sg;
        g_Phn[k * LDIM + lane] = -0.5f * pr;
        g_MP[k * LDIM + lane] = mu * pr;
        ld = logf(sg);
        qd = mu * mu * pr;
    }
    #pragma unroll
    for (int o = 16; o; o >>= 1) {
        ld += __shfl_xor_sync(0xffffffffu, ld, o);
        qd += __shfl_xor_sync(0xffffffffu, qd, o);
    }
    if (lane == 0)
        g_C[k] = logf(g_w[k]) - 0.5f * (LOG_PI_C + ld + qd) + SHIFT;
}

// ---------------- E-step: x-only smem tile, warp-per-2-rows, fixed-shift softmax
// n[k] = C'[k] + sum_l x * (MP[k][l] + x * Phn[k][l]);  C' includes +SHIFT.
// No per-row max pass: exp directly; underflowed components are truly negligible.
__global__ void __launch_bounds__(128) k_estep(const float* __restrict__ x) {
    __shared__ __align__(16) float xt[TILE_E * 28];
    __shared__ float sll[4];
    int tid = threadIdx.x;
    int lane = tid & 31;
    int warp = tid >> 5;

    // zero pads once (staging never writes c>=26)
    for (int r = tid; r < TILE_E; r += 128) {
        xt[r * 28 + 26] = 0.f;
        xt[r * 28 + 27] = 0.f;
    }

    float MP0[28], Ph0[28], MP1[28], Ph1[28];
    #pragma unroll
    for (int l = 0; l < LDIM; l++) {
        MP0[l] = g_MP[lane * LDIM + l];
        Ph0[l] = g_Phn[lane * LDIM + l];
        MP1[l] = g_MP[(lane + 32) * LDIM + l];
        Ph1[l] = g_Phn[(lane + 32) * LDIM + l];
    }
    #pragma unroll
    for (int l = LDIM; l < 28; l++) {
        MP0[l] = 0.f; Ph0[l] = 0.f; MP1[l] = 0.f; Ph1[l] = 0.f;
    }
    float C0 = g_C[lane], C1 = g_C[lane + 32];
    float llacc = 0.f;

    for (int t = blockIdx.x; t < BN / TILE_E; t += NBLK_E) {
        int rowbase = t * TILE_E;
        __syncthreads();
        // stage 128 rows x 26 floats = 832 float4
        const float4* src = (const float4*)(x + (size_t)rowbase * LDIM);
        for (int i = tid; i < TILE_E * LDIM / 4; i += 128) {
            float4 v = src[i];
            int e = i * 4;
            float vv[4] = {v.x, v.y, v.z, v.w};
            #pragma unroll
            for (int j = 0; j < 4; j++) {
                int idx = e + j;
                int r = idx / LDIM, c = idx % LDIM;
                xt[r * 28 + c] = vv[j];
            }
        }
        __syncthreads();
        #pragma unroll 1
        for (int it = 0; it < 16; it++) {
            int r0 = warp * 32 + it * 2;
            const float4* A = (const float4*)(xt + r0 * 28);
            const float4* B = (const float4*)(xt + (r0 + 1) * 28);
            float n00 = C0, n01 = C1, n10 = C0, n11 = C1;
            #pragma unroll
            for (int i = 0; i < 7; i++) {
                float4 a = A[i];
                float4 b = B[i];
                #pragma unroll
                for (int j = 0; j < 4; j++) {
                    int l = 4 * i + j;
                    float ax = j == 0 ? a.x : j == 1 ? a.y : j == 2 ? a.z : a.w;
                    float bx = j == 0 ? b.x : j == 1 ? b.y : j == 2 ? b.z : b.w;
                    float t0 = fmaf(ax, Ph0[l], MP0[l]);
                    n00 = fmaf(ax, t0, n00);
                    float t1 = fmaf(ax, Ph1[l], MP1[l]);
                    n01 = fmaf(ax, t1, n01);
                    float u0 = fmaf(bx, Ph0[l], MP0[l]);
                    n10 = fmaf(bx, u0, n10);
                    float u1 = fmaf(bx, Ph1[l], MP1[l]);
                    n11 = fmaf(bx, u1, n11);
                }
            }
            float e00 = __expf(n00), e01 = __expf(n01);
            float e10 = __expf(n10), e11 = __expf(n11);
            float s0 = e00 + e01, s1 = e10 + e11;
            #pragma unroll
            for (int o = 16; o; o >>= 1) {
                s0 += __shfl_xor_sync(0xffffffffu, s0, o);
                s1 += __shfl_xor_sync(0xffffffffu, s1, o);
            }
            float rs0 = __frcp_rn(s0), rs1 = __frcp_rn(s1);
            float* P0 = g_post + (size_t)(rowbase + r0) * KCOMP;
            P0[lane]              = e00 * rs0;
            P0[lane + 32]         = e01 * rs0;
            P0[KCOMP + lane]      = e10 * rs1;
            P0[KCOMP + lane + 32] = e11 * rs1;
            if (lane == 0)
                llacc += (__logf(s0) - SHIFT) + (__logf(s1) - SHIFT);
        }
    }
    if (lane == 0) sll[warp] = llacc;
    __syncthreads();
    if (tid == 0)
        g_llp[blockIdx.x] = sll[0] + sll[1] + sll[2] + sll[3];
}

// ---------------- M-step stats: warp = (khalf, h, rowgrp); p staged in smem -
// thread: k = lane + 32*khalf; h=0 accumulates z+px over x, h=1 pxx over x^2
__global__ void __launch_bounds__(256, 4) k_mstat(const float* __restrict__ x) {
    __shared__ __align__(16) float xs[TILE_M][28];
    __shared__ __align__(16) float x2s[TILE_M][28];
    __shared__ __align__(16) float ps[TILE_M][KCOMP];
    __shared__ float comb[128 * 29];
    int tid = threadIdx.x;
    int lane = tid & 31;
    int warp = tid >> 5;
    int khalf = warp & 1;
    int h = (warp >> 1) & 1;
    int rgrp = warp >> 2;            // 0 or 1 -> 16 rows each
    int k = lane + (khalf << 5);

    if (tid < TILE_M) {
        xs[tid][26] = 0.f;  xs[tid][27] = 0.f;
        x2s[tid][26] = 0.f; x2s[tid][27] = 0.f;
    }

    float z = 0.f;
    float acc[28];
    #pragma unroll
    for (int j = 0; j < 28; j++) acc[j] = 0.f;

    for (int t = blockIdx.x; t < NTILE_M; t += NBLK_M) {
        int rowbase = t * TILE_M;
        __syncthreads();
        // stage 32 rows x 26 floats = 208 float4
        if (tid < 208) {
            float4 v = ((const float4*)(x + (size_t)rowbase * LDIM))[tid];
            int e = tid * 4;
            float vv[4] = {v.x, v.y, v.z, v.w};
            #pragma unroll
            for (int j = 0; j < 4; j++) {
                int idx = e + j;
                int r = idx / LDIM, c = idx % LDIM;
                xs[r][c] = vv[j];
                x2s[r][c] = vv[j] * vv[j];
            }
        }
        // stage 32 rows x 64 posteriors = 512 float4
        {
            const float4* psrc = (const float4*)(g_post + (size_t)rowbase * KCOMP);
            float4 p0 = psrc[tid];
            float4 p1 = psrc[tid + 256];
            ((float4*)ps)[tid] = p0;
            ((float4*)ps)[tid + 256] = p1;
        }
        __syncthreads();
        #pragma unroll
        for (int rr = 0; rr < 16; rr++) {
            int r = rgrp * 16 + rr;
            float p = ps[r][k];
            z += p;
            const float4* V = (const float4*)(h ? x2s[r] : xs[r]);
            #pragma unroll
            for (int i = 0; i < 7; i++) {
                float4 v = V[i];
                acc[4*i]   = fmaf(p, v.x, acc[4*i]);
                acc[4*i+1] = fmaf(p, v.y, acc[4*i+1]);
                acc[4*i+2] = fmaf(p, v.z, acc[4*i+2]);
                acc[4*i+3] = fmaf(p, v.w, acc[4*i+3]);
            }
        }
    }
    // combine rgrp=1 into rgrp=0 via smem, then one partial slot per block
    __syncthreads();
    if (rgrp == 1) {
        float* c = comb + ((warp & 3) * 32 + lane) * 29;
        #pragma unroll
        for (int j = 0; j < 26; j++) c[j] = acc[j];
        c[26] = z;
    }
    __syncthreads();
    if (rgrp == 0) {
        const float* c = comb + (warp * 32 + lane) * 29;
        #pragma unroll
        for (int j = 0; j < 26; j++) acc[j] += c[j];
        z += c[26];
        float* dst = g_part + ((size_t)blockIdx.x * KCOMP + k) * 54;
        if (h == 0) {
            dst[0] = z;
            #pragma unroll
            for (int j = 0; j < 26; j++) dst[1 + j] = acc[j];
        } else {
            #pragma unroll
            for (int j = 0; j < 26; j++) dst[27 + j] = acc[j];
        }
    }
}

// ---------------- reduce partials: one block per (k, slot-half) ----------------
__global__ void __launch_bounds__(256) k_reduce() {
    __shared__ float red[4][54];
    int bk = blockIdx.x >> 1;
    int half = blockIdx.x & 1;
    int tid = threadIdx.x;
    int j = tid & 63;
    int s = tid >> 6;
    if (j < 54) {
        float acc = 0.f;
        int base = half * RHALF;
        for (int slot = s; slot < RHALF; slot += 4)
            acc += g_part[((size_t)(base + slot) * KCOMP + bk) * 54 + j];
        red[s][j] = acc;
    }
    __syncthreads();
    if (tid < 54)
        g_stat2[half][bk * 54 + tid] = red[0][tid] + red[1][tid] + red[2][tid] + red[3][tid];
}

// ---------------- M-step finalize + fused prep ----------------
__global__ void __launch_bounds__(256) k_mstep() {
    __shared__ float s_w[KCOMP];
    __shared__ float s_ab[2];
    __shared__ float s_llp[64];
    int tid = threadIdx.x;

    if (tid < KCOMP) {
        float zk = g_stat2[0][tid * 54] + g_stat2[1][tid * 54];
        s_w[tid] = fmaxf(zk * (1.0f / BN), WFLOOR);
        float l = 0.f;
        for (int i = tid; i < NBLK_E; i += 64) l += g_llp[i];
        s_llp[tid] = l;
    }
    __syncthreads();
    if (tid == 0) {
        float sum = 0.f, ll = 0.f;
        for (int k = 0; k < KCOMP; k++) { sum += s_w[k]; ll += s_llp[k]; }
        float sf = WFLOOR * KCOMP;
        float a = (1.0f - sf) / (sum - sf);
        s_ab[0] = a;
        s_ab[1] = WFLOOR * (1.0f - a);
        g_ll = ll;
    }
    __syncthreads();
    if (tid < KCOMP) g_w[tid] = s_ab[0] * s_w[tid] + s_ab[1];

    for (int idx = tid; idx < KCOMP * LDIM; idx += 256) {
        int k = idx / LDIM, l = idx % LDIM;
        float z = g_stat2[0][k * 54] + g_stat2[1][k * 54];
        float zi = 1.0f / z;
        float px = g_stat2[0][k * 54 + 1 + l] + g_stat2[1][k * 54 + 1 + l];
        float pxx = g_stat2[0][k * 54 + 27 + l] + g_stat2[1][k * 54 + 27 + l];
        float mu = px * zi;
        float sg = fmaxf(pxx * zi - mu * mu, VFLOOR);
        g_mu[idx] = mu;
        g_sig[idx] = sg;
    }
    __syncthreads();

    int warp = tid >> 5, lane = tid & 31;
    for (int k = warp; k < KCOMP; k += 8) {
        float ld = 0.f, qd = 0.f;
        if (lane < LDIM) {
            float sg = g_sig[k * LDIM + lane];
            float mu = g_mu[k * LDIM + lane];
            float pr = 1.0f / sg;
            g_Phn[k * LDIM + lane] = -0.5f * pr;
            g_MP[k * LDIM + lane] = mu * pr;
            ld = logf(sg);
            qd = mu * mu * pr;
        }
        #pragma unroll
        for (int o = 16; o; o >>= 1) {
            ld += __shfl_xor_sync(0xffffffffu, ld, o);
            qd += __shfl_xor_sync(0xffffffffu, qd, o);
        }
        if (lane == 0)
            g_C[k] = logf(g_w[k]) - 0.5f * (LOG_PI_C + ld + qd) + SHIFT;
    }
}

// ---------------- output: w | mu | diag-expanded sigma | ll ----------------
__global__ void k_write(float* __restrict__ out) {
    int i = blockIdx.x * 256 + threadIdx.x;
    if (i >= OUT_N) return;
    float v;
    if (i < KCOMP) {
        v = g_w[i];
    } else if (i < KCOMP + KCOMP * LDIM) {
        v = g_mu[i - KCOMP];
    } else if (i < KCOMP + KCOMP * LDIM + KCOMP * LDIM * LDIM) {
        int j = i - (KCOMP + KCOMP * LDIM);
        int k = j / (LDIM * LDIM);
        int rc = j % (LDIM * LDIM);
        int r = rc / LDIM, c = rc % LDIM;
        v = (r == c) ? g_sig[k * LDIM + r] : 0.f;
    } else {
        v = g_ll;
    }
    out[i] = v;
}

extern "C" void kernel_launch(void* const* d_in, const int* in_sizes, int n_in,
                              void* d_out, int out_size) {
    const float* x   = (const float*)d_in[0];
    const float* w0  = (const float*)d_in[1];
    const float* mu0 = (const float*)d_in[2];
    const float* s0  = (const float*)d_in[3];
    float* out = (float*)d_out;

    k_init<<<1, 256>>>(w0, mu0, s0);
    k_prep<<<KCOMP, 32>>>();
    for (int it = 0; it < NITER; it++) {
        k_estep<<<NBLK_E, 128>>>(x);
        k_mstat<<<NBLK_M, 256>>>(x);
        k_reduce<<<KCOMP * 2, 256>>>();
        k_mstep<<<1, 256>>>();
    }
    k_write<<<(OUT_N + 255) / 256, 256>>>(out);
}